// round 11
// baseline (speedup 1.0000x reference)
#include <cuda_runtime.h>

typedef unsigned long long u64;
typedef ulonglong2 ull2;
#define NSL 384
#define SLC 12800
#define ESL 160000
#define VN  400
#define CH  32
#define LL  12

__device__ __align__(16) float g_Xt [NSL*SLC];
__device__ __align__(16) float g_X1 [NSL*SLC];
__device__ __align__(16) float g_X2 [NSL*SLC];
__device__ __align__(16) float g_H1a[NSL*SLC];
__device__ __align__(16) float g_H1b[NSL*SLC];
__device__ __align__(16) float g_H2a[NSL*SLC];
__device__ __align__(16) float g_H2b[NSL*SLC];
__device__ __align__(16) float g_R1 [NSL*VN];
__device__ __align__(16) float g_R2 [NSL*VN];
__device__ __align__(16) float g_E  [NSL*ESL];
__device__ __align__(16) float g_ET [NSL*ESL];

__device__ __forceinline__ void fma2(u64 &d, u64 a, u64 b) {
    asm("fma.rn.f32x2 %0, %1, %2, %0;" : "+l"(d) : "l"(a), "l"(b));
}
__device__ __forceinline__ u64 pk2(float x) {
    u64 r; asm("mov.b64 %0, {%1, %1};" : "=l"(r) : "f"(x)); return r;
}
__device__ __forceinline__ float2 up2(u64 a) {
    float2 r; asm("mov.b64 {%0, %1}, %2;" : "=f"(r.x), "=f"(r.y) : "l"(a)); return r;
}

// transpose x -> g_Xt[s][c][v]; contiguous 48B reads, coalesced scatter.
__global__ __launch_bounds__(256) void k_tr(const float* __restrict__ x) {
    int id = blockIdx.x * 256 + threadIdx.x;  // (n*32+c)*400+v
    if (id >= 409600) return;
    const float4* xp = (const float4*)x;
    float4 a = xp[id * 3], b = xp[id * 3 + 1], c4 = xp[id * 3 + 2];
    float vals[12] = {a.x, a.y, a.z, a.w, b.x, b.y, b.z, b.w,
                      c4.x, c4.y, c4.z, c4.w};
    int n = id / SLC, cv = id - n * SLC;
    float* base = g_Xt + cv;
    #pragma unroll
    for (int l = 0; l < 12; l++)
        base[(size_t)(n * LL + l) * SLC] = vals[l];
}

// X1 = tanh(W1 Xt + b1), X2 = tanh(W2 Xt + b2)
__global__ __launch_bounds__(256) void k_conv(const float* __restrict__ w1,
                                              const float* __restrict__ b1,
                                              const float* __restrict__ w2,
                                              const float* __restrict__ b2) {
    __shared__ float w1s[1024], w2s[1024], b1s[32], b2s[32];
    int s = blockIdx.x, t = threadIdx.x;
    for (int i = t; i < 1024; i += 256) { w1s[i] = w1[i]; w2s[i] = w2[i]; }
    if (t < 32) { b1s[t] = b1[t]; b2s[t] = b2[t]; }
    __syncthreads();
    const float* xt = g_Xt + (size_t)s * SLC;
    for (int i = t; i < SLC; i += 256) {
        int c = i / VN, v = i - c * VN;
        float a1 = b1s[c], a2 = b2s[c];
        #pragma unroll
        for (int k = 0; k < 32; k++) {
            float xv = xt[k * VN + v];
            a1 += w1s[c * 32 + k] * xv;
            a2 += w2s[c * 32 + k] * xv;
        }
        g_X1[(size_t)s * SLC + i] = tanhf(a1);
        g_X2[(size_t)s * SLC + i] = tanhf(a2);
    }
}

// Fused E-builder: z=0 -> E=exp(X1^T X2), R1; z=1 -> ET, R2.
// grid (13, NSL, 2), block 128. t<100: vh=t&1 (16 v's), oct=t>>1 (8 w's).
__global__ __launch_bounds__(128) void k2(const float* __restrict__ X1p,
                                          const float* __restrict__ X2p,
                                          float* __restrict__ Eo1,
                                          float* __restrict__ Ro1,
                                          float* __restrict__ Eo2,
                                          float* __restrict__ Ro2) {
    __shared__ u64 As2[1024];     // [k][vl] pk2 singles
    __shared__ float red[128];    // [warp][vh*16+lv]
    int s = blockIdx.y, vbase = blockIdx.x * 32, z = blockIdx.z;
    const float* A = z ? X2p : X1p;
    const float* B = z ? X1p : X2p;
    float* Eo = z ? Eo2 : Eo1;
    float* Ro = z ? Ro2 : Ro1;
    int t = threadIdx.x, lam = t & 31, wp = t >> 5;
    for (int i = t; i < 1024; i += 128) {
        int k = i >> 5, vl = i & 31, v = vbase + vl;
        As2[i] = pk2(v < VN ? A[(size_t)s * SLC + k * VN + v] : 0.f);
    }
    __syncthreads();
    bool act = (t < 100);
    int vh = t & 1, oct = t >> 1;
    int w8 = act ? oct * 8 : 0;
    int vof = vh * 16;
    u64 acc[16][4];
    #pragma unroll
    for (int i = 0; i < 16; i++)
        #pragma unroll
        for (int j = 0; j < 4; j++) acc[i][j] = 0;
    const float* Bb = B + (size_t)s * SLC;
    ull2 bL = *(const ull2*)(Bb + w8);
    ull2 bH = *(const ull2*)(Bb + w8 + 4);
    for (int k = 0; k < 32; k++) {
        ull2 nL, nH;
        int kn = (k + 1 < 32) ? k + 1 : 0;
        nL = *(const ull2*)(Bb + kn * VN + w8);
        nH = *(const ull2*)(Bb + kn * VN + w8 + 4);
        #pragma unroll
        for (int vp = 0; vp < 8; vp++) {
            ull2 a = *(const ull2*)&As2[k * 32 + vof + 2 * vp];
            fma2(acc[2 * vp][0], a.x, bL.x);
            fma2(acc[2 * vp][1], a.x, bL.y);
            fma2(acc[2 * vp][2], a.x, bH.x);
            fma2(acc[2 * vp][3], a.x, bH.y);
            fma2(acc[2 * vp + 1][0], a.y, bL.x);
            fma2(acc[2 * vp + 1][1], a.y, bL.y);
            fma2(acc[2 * vp + 1][2], a.y, bH.x);
            fma2(acc[2 * vp + 1][3], a.y, bH.y);
        }
        bL = nL; bH = nH;
    }
    float prs[16];
    float* Erow = Eo + (size_t)s * ESL;
    #pragma unroll
    for (int lv = 0; lv < 16; lv++) {
        int v = vbase + vof + lv;
        float2 p0 = up2(acc[lv][0]), p1 = up2(acc[lv][1]);
        float2 p2 = up2(acc[lv][2]), p3 = up2(acc[lv][3]);
        float4 e0, e1;
        e0.x = __expf(p0.x); e0.y = __expf(p0.y);
        e0.z = __expf(p1.x); e0.w = __expf(p1.y);
        e1.x = __expf(p2.x); e1.y = __expf(p2.y);
        e1.z = __expf(p3.x); e1.w = __expf(p3.y);
        prs[lv] = act ? (e0.x + e0.y + e0.z + e0.w) +
                        (e1.x + e1.y + e1.z + e1.w) : 0.f;
        if (act && v < VN) {
            *(float4*)(Erow + (size_t)v * VN + w8) = e0;
            *(float4*)(Erow + (size_t)v * VN + w8 + 4) = e1;
        }
    }
    #pragma unroll
    for (int lv = 0; lv < 16; lv++) {
        prs[lv] += __shfl_xor_sync(0xffffffffu, prs[lv], 2);
        prs[lv] += __shfl_xor_sync(0xffffffffu, prs[lv], 4);
        prs[lv] += __shfl_xor_sync(0xffffffffu, prs[lv], 8);
        prs[lv] += __shfl_xor_sync(0xffffffffu, prs[lv], 16);
    }
    if (lam < 2) {
        #pragma unroll
        for (int lv = 0; lv < 16; lv++)
            red[wp * 32 + vh * 16 + lv] = prs[lv];
    }
    __syncthreads();
    if (t < 32) {
        float sum = red[t] + red[32 + t] + red[64 + t] + red[96 + t];
        int v = vbase + t;
        if (v < VN) Ro[(size_t)s * VN + v] = sum;
    }
}

// Fused double diffusion step: Ha = 0.05X + 0.95*(X/R)E; Hb from Ha.
// grid (NSL, 2 sides, 2 halves), block 64, t<50 owns w-oct x 16 channels.
// dyn smem = 400*4 + 16*400*8 = 52800 B.
__global__ __launch_bounds__(64) void kd(const float* __restrict__ E1,
                                         const float* __restrict__ Rr1,
                                         const float* __restrict__ E2,
                                         const float* __restrict__ Rr2,
                                         float* __restrict__ Ho1a,
                                         float* __restrict__ Ho1b,
                                         float* __restrict__ Ho2a,
                                         float* __restrict__ Ho2b) {
    extern __shared__ float smf[];
    float* rinv = smf;              // 400
    u64* hs2 = (u64*)(smf + VN);    // [16][400] pk2(H/R)
    int s = blockIdx.x, side = blockIdx.y, half = blockIdx.z;
    const float* Em = side ? E2 : E1;
    const float* Rm = side ? Rr2 : Rr1;
    float* Hoa = side ? Ho2a : Ho1a;
    float* Hob = side ? Ho2b : Ho1b;
    int t = threadIdx.x;
    size_t cbase = (size_t)s * SLC + half * 16 * VN;
    for (int i = t; i < VN; i += 64) rinv[i] = 1.0f / Rm[(size_t)s * VN + i];
    __syncthreads();
    const float* Xb = g_Xt + cbase;
    for (int i = t; i < 16 * VN; i += 64)
        hs2[i] = pk2(Xb[i] * rinv[i % VN]);
    __syncthreads();

    const float* Eb = Em + (size_t)s * ESL;
    bool act = (t < 50);
    int w8 = act ? t * 8 : 0;
    for (int step = 0; step < 2; step++) {
        u64 acc[16][4];
        if (act) {
            #pragma unroll
            for (int c = 0; c < 16; c++)
                #pragma unroll
                for (int j = 0; j < 4; j++) acc[c][j] = 0;
            ull2 caL = *(const ull2*)(Eb + w8);
            ull2 caH = *(const ull2*)(Eb + w8 + 4);
            ull2 cbL = *(const ull2*)(Eb + VN + w8);
            ull2 cbH = *(const ull2*)(Eb + VN + w8 + 4);
            for (int v = 0; v < VN; v += 2) {
                int vn = (v + 2 < VN) ? v + 2 : 0;
                ull2 naL = *(const ull2*)(Eb + (size_t)vn * VN + w8);
                ull2 naH = *(const ull2*)(Eb + (size_t)vn * VN + w8 + 4);
                ull2 nbL = *(const ull2*)(Eb + (size_t)(vn + 1) * VN + w8);
                ull2 nbH = *(const ull2*)(Eb + (size_t)(vn + 1) * VN + w8 + 4);
                #pragma unroll
                for (int c = 0; c < 16; c++) {
                    ull2 h = *(const ull2*)&hs2[c * VN + v];
                    fma2(acc[c][0], h.x, caL.x);
                    fma2(acc[c][1], h.x, caL.y);
                    fma2(acc[c][2], h.x, caH.x);
                    fma2(acc[c][3], h.x, caH.y);
                    fma2(acc[c][0], h.y, cbL.x);
                    fma2(acc[c][1], h.y, cbL.y);
                    fma2(acc[c][2], h.y, cbH.x);
                    fma2(acc[c][3], h.y, cbH.y);
                }
                caL = naL; caH = naH; cbL = nbL; cbH = nbH;
            }
        }
        __syncthreads();   // mainloop reads of hs2 complete
        if (act) {
            float* Ob = (step == 0 ? Hoa : Hob) + cbase;
            #pragma unroll
            for (int c = 0; c < 16; c++) {
                float4 x0 = *(const float4*)(Xb + c * VN + w8);
                float4 x1 = *(const float4*)(Xb + c * VN + w8 + 4);
                float2 p0 = up2(acc[c][0]), p1 = up2(acc[c][1]);
                float2 p2 = up2(acc[c][2]), p3 = up2(acc[c][3]);
                float4 r0, r1;
                r0.x = 0.05f * x0.x + 0.95f * p0.x;
                r0.y = 0.05f * x0.y + 0.95f * p0.y;
                r0.z = 0.05f * x0.z + 0.95f * p1.x;
                r0.w = 0.05f * x0.w + 0.95f * p1.y;
                r1.x = 0.05f * x1.x + 0.95f * p2.x;
                r1.y = 0.05f * x1.y + 0.95f * p2.y;
                r1.z = 0.05f * x1.z + 0.95f * p3.x;
                r1.w = 0.05f * x1.w + 0.95f * p3.y;
                *(float4*)(Ob + c * VN + w8) = r0;
                *(float4*)(Ob + c * VN + w8 + 4) = r1;
                if (step == 0) {
                    hs2[c * VN + w8 + 0] = pk2(r0.x * rinv[w8 + 0]);
                    hs2[c * VN + w8 + 1] = pk2(r0.y * rinv[w8 + 1]);
                    hs2[c * VN + w8 + 2] = pk2(r0.z * rinv[w8 + 2]);
                    hs2[c * VN + w8 + 3] = pk2(r0.w * rinv[w8 + 3]);
                    hs2[c * VN + w8 + 4] = pk2(r1.x * rinv[w8 + 4]);
                    hs2[c * VN + w8 + 5] = pk2(r1.y * rinv[w8 + 5]);
                    hs2[c * VN + w8 + 6] = pk2(r1.z * rinv[w8 + 6]);
                    hs2[c * VN + w8 + 7] = pk2(r1.w * rinv[w8 + 7]);
                }
            }
        }
        __syncthreads();   // hs2 repack visible before step 2
    }
}

// out = b1+b2 + (Wm1x+Wm2x)Xt + Wm1a*H1a + Wm1b*H1b + Wm2a*H2a + Wm2b*H2b
__global__ __launch_bounds__(256) void k_mlp(const float* __restrict__ w1,
                                             const float* __restrict__ b1,
                                             const float* __restrict__ w2,
                                             const float* __restrict__ b2,
                                             float* __restrict__ out) {
    __shared__ float wxc[1024], wa1[2048], wa2[2048], bs[32];
    int s = blockIdx.x, t = threadIdx.x;
    int n = s / LL, l = s - n * LL;
    for (int i = t; i < 1024; i += 256) {
        int o = i >> 5, c = i & 31;
        wxc[i] = w1[o * 96 + c] + w2[o * 96 + c];
    }
    for (int i = t; i < 2048; i += 256) {
        int o = i >> 6, c = i & 63;
        wa1[i] = w1[o * 96 + 32 + c];
        wa2[i] = w2[o * 96 + 32 + c];
    }
    if (t < 32) bs[t] = b1[t] + b2[t];
    __syncthreads();
    size_t sb = (size_t)s * SLC;
    const float4* Xt4 = (const float4*)(g_Xt  + sb);
    const float4* A14 = (const float4*)(g_H1a + sb);
    const float4* B14 = (const float4*)(g_H1b + sb);
    const float4* A24 = (const float4*)(g_H2a + sb);
    const float4* B24 = (const float4*)(g_H2b + sb);
    for (int qd = t; qd < 3200; qd += 256) {
        int o = qd / 100, vq = qd - o * 100;
        float bz = bs[o];
        float4 a; a.x = bz; a.y = bz; a.z = bz; a.w = bz;
        #pragma unroll 8
        for (int c = 0; c < 32; c++) {
            int idx = c * 100 + vq;
            float4 xv = Xt4[idx];
            float w = wxc[o * 32 + c];
            a.x += w * xv.x; a.y += w * xv.y; a.z += w * xv.z; a.w += w * xv.w;
            float4 h1 = A14[idx];
            w = wa1[o * 64 + c];
            a.x += w * h1.x; a.y += w * h1.y; a.z += w * h1.z; a.w += w * h1.w;
            float4 h1b = B14[idx];
            w = wa1[o * 64 + 32 + c];
            a.x += w * h1b.x; a.y += w * h1b.y; a.z += w * h1b.z; a.w += w * h1b.w;
            float4 h2 = A24[idx];
            w = wa2[o * 64 + c];
            a.x += w * h2.x; a.y += w * h2.y; a.z += w * h2.z; a.w += w * h2.w;
            float4 h2b = B24[idx];
            w = wa2[o * 64 + 32 + c];
            a.x += w * h2b.x; a.y += w * h2b.y; a.z += w * h2b.z; a.w += w * h2b.w;
        }
        int v = vq * 4;
        size_t ob = ((size_t)(n * CH + o) * VN + v) * LL + l;
        out[ob]          = a.x;
        out[ob + LL]     = a.y;
        out[ob + 2 * LL] = a.z;
        out[ob + 3 * LL] = a.w;
    }
}

extern "C" void kernel_launch(void* const* d_in, const int* in_sizes, int n_in,
                              void* d_out, int out_size) {
    const float* x   = (const float*)d_in[0];
    const float* wl1 = (const float*)d_in[1];
    const float* bl1 = (const float*)d_in[2];
    const float* wl2 = (const float*)d_in[3];
    const float* bl2 = (const float*)d_in[4];
    const float* wm1 = (const float*)d_in[5];
    const float* bm1 = (const float*)d_in[6];
    const float* wm2 = (const float*)d_in[7];
    const float* bm2 = (const float*)d_in[8];
    float* out = (float*)d_out;

    const int dsm = VN * 4 + 16 * VN * 8;   // 52800 B
    static bool attr_done = false;
    if (!attr_done) {
        cudaFuncSetAttribute(kd, cudaFuncAttributeMaxDynamicSharedMemorySize, dsm);
        attr_done = true;
    }

    float *E, *ET, *R1, *R2, *X1, *X2, *H1a, *H1b, *H2a, *H2b;
    cudaGetSymbolAddress((void**)&E,  g_E);
    cudaGetSymbolAddress((void**)&ET, g_ET);
    cudaGetSymbolAddress((void**)&R1, g_R1);
    cudaGetSymbolAddress((void**)&R2, g_R2);
    cudaGetSymbolAddress((void**)&X1, g_X1);
    cudaGetSymbolAddress((void**)&X2, g_X2);
    cudaGetSymbolAddress((void**)&H1a, g_H1a);
    cudaGetSymbolAddress((void**)&H1b, g_H1b);
    cudaGetSymbolAddress((void**)&H2a, g_H2a);
    cudaGetSymbolAddress((void**)&H2b, g_H2b);

    k_tr<<<1600, 256>>>(x);
    k_conv<<<NSL, 256>>>(wl1, bl1, wl2, bl2);
    k2<<<dim3(13, NSL, 2), 128>>>(X1, X2, E, R1, ET, R2);
    kd<<<dim3(NSL, 2, 2), 64, dsm>>>(E, R1, ET, R2, H1a, H1b, H2a, H2b);
    k_mlp<<<NSL, 256>>>(wm1, bm1, wm2, bm2, out);
}

// round 13
// speedup vs baseline: 1.5945x; 1.5945x over previous
#include <cuda_runtime.h>

typedef unsigned long long u64;
typedef ulonglong2 ull2;
#define NSL 384
#define SLC 12800
#define ESL 160000
#define VN  400
#define CH  32
#define LL  12

__device__ __align__(16) float g_Xt [NSL*SLC];
__device__ __align__(16) float g_X1 [NSL*SLC];
__device__ __align__(16) float g_X2 [NSL*SLC];
__device__ __align__(16) float g_H1a[NSL*SLC];
__device__ __align__(16) float g_H1b[NSL*SLC];
__device__ __align__(16) float g_H2a[NSL*SLC];
__device__ __align__(16) float g_H2b[NSL*SLC];
__device__ __align__(16) float g_R1 [NSL*VN];
__device__ __align__(16) float g_R2 [NSL*VN];
__device__ __align__(16) float g_E  [NSL*ESL];
__device__ __align__(16) float g_ET [NSL*ESL];

__device__ __forceinline__ void fma2(u64 &d, u64 a, u64 b) {
    asm("fma.rn.f32x2 %0, %1, %2, %0;" : "+l"(d) : "l"(a), "l"(b));
}
__device__ __forceinline__ u64 pk2(float x) {
    u64 r; asm("mov.b64 %0, {%1, %1};" : "=l"(r) : "f"(x)); return r;
}
__device__ __forceinline__ float2 up2(u64 a) {
    float2 r; asm("mov.b64 {%0, %1}, %2;" : "=f"(r.x), "=f"(r.y) : "l"(a)); return r;
}

// transpose x -> g_Xt[s][c][v]; contiguous 48B reads, coalesced scatter.
__global__ __launch_bounds__(256) void k_tr(const float* __restrict__ x) {
    int id = blockIdx.x * 256 + threadIdx.x;  // (n*32+c)*400+v
    if (id >= 409600) return;
    const float4* xp = (const float4*)x;
    float4 a = xp[id * 3], b = xp[id * 3 + 1], c4 = xp[id * 3 + 2];
    float vals[12] = {a.x, a.y, a.z, a.w, b.x, b.y, b.z, b.w,
                      c4.x, c4.y, c4.z, c4.w};
    int n = id / SLC, cv = id - n * SLC;
    float* base = g_Xt + cv;
    #pragma unroll
    for (int l = 0; l < 12; l++)
        base[(size_t)(n * LL + l) * SLC] = vals[l];
}

// X1 = tanh(W1 Xt + b1), X2 = tanh(W2 Xt + b2)
__global__ __launch_bounds__(256) void k_conv(const float* __restrict__ w1,
                                              const float* __restrict__ b1,
                                              const float* __restrict__ w2,
                                              const float* __restrict__ b2) {
    __shared__ float w1s[1024], w2s[1024], b1s[32], b2s[32];
    int s = blockIdx.x, t = threadIdx.x;
    for (int i = t; i < 1024; i += 256) { w1s[i] = w1[i]; w2s[i] = w2[i]; }
    if (t < 32) { b1s[t] = b1[t]; b2s[t] = b2[t]; }
    __syncthreads();
    const float* xt = g_Xt + (size_t)s * SLC;
    for (int i = t; i < SLC; i += 256) {
        int c = i / VN, v = i - c * VN;
        float a1 = b1s[c], a2 = b2s[c];
        #pragma unroll
        for (int k = 0; k < 32; k++) {
            float xv = xt[k * VN + v];
            a1 += w1s[c * 32 + k] * xv;
            a2 += w2s[c * 32 + k] * xv;
        }
        g_X1[(size_t)s * SLC + i] = tanhf(a1);
        g_X2[(size_t)s * SLC + i] = tanhf(a2);
    }
}

// Fused E-builder: z=0 -> E=exp(X1^T X2), R1; z=1 -> ET, R2.
// grid (13, NSL, 2), block 256, 2 CTAs/SM.
// Halves: t<128 -> v rows vbase..+15, t>=128 -> vbase+16..+31.
// Within half, u<100 owns w-quad 4u. A (pk2) and B both staged in smem.
__global__ __launch_bounds__(256, 2) void k2(const float* __restrict__ X1p,
                                             const float* __restrict__ X2p,
                                             float* __restrict__ Eo1,
                                             float* __restrict__ Ro1,
                                             float* __restrict__ Eo2,
                                             float* __restrict__ Ro2) {
    __shared__ u64 As2[1024];       // [k][vl] pk2(A), 8KB
    __shared__ float Bs[SLC];       // full B slice, 51.2KB
    __shared__ float red[128];      // [warp][lv]
    int s = blockIdx.y, vbase = blockIdx.x * 32, z = blockIdx.z;
    const float* A = z ? X2p : X1p;
    const float* B = z ? X1p : X2p;
    float* Eo = z ? Eo2 : Eo1;
    float* Ro = z ? Ro2 : Ro1;
    int t = threadIdx.x, lam = t & 31, wp = t >> 5;
    for (int i = t; i < 1024; i += 256) {
        int k = i >> 5, vl = i & 31, v = vbase + vl;
        As2[i] = pk2(v < VN ? A[(size_t)s * SLC + k * VN + v] : 0.f);
    }
    {
        const float4* Bg = (const float4*)(B + (size_t)s * SLC);
        float4* Bs4 = (float4*)Bs;
        for (int i = t; i < SLC / 4; i += 256) Bs4[i] = Bg[i];
    }
    __syncthreads();
    int half = t >> 7, u = t & 127;
    bool act = (u < 100);
    int w4 = act ? u * 4 : 0;
    int vof = half * 16;
    u64 acc[16][2];
    #pragma unroll
    for (int i = 0; i < 16; i++) { acc[i][0] = 0; acc[i][1] = 0; }
    #pragma unroll 4
    for (int k = 0; k < 32; k++) {
        ull2 bq = *(const ull2*)(Bs + k * VN + w4);   // (b0,b1),(b2,b3)
        #pragma unroll
        for (int vp = 0; vp < 8; vp++) {
            ull2 a = *(const ull2*)&As2[k * 32 + vof + 2 * vp];
            fma2(acc[2 * vp][0], a.x, bq.x);
            fma2(acc[2 * vp][1], a.x, bq.y);
            fma2(acc[2 * vp + 1][0], a.y, bq.x);
            fma2(acc[2 * vp + 1][1], a.y, bq.y);
        }
    }
    float prs[16];
    float* Erow = Eo + (size_t)s * ESL;
    #pragma unroll
    for (int lv = 0; lv < 16; lv++) {
        int v = vbase + vof + lv;
        float2 p0 = up2(acc[lv][0]), p1 = up2(acc[lv][1]);
        float4 e;
        e.x = __expf(p0.x); e.y = __expf(p0.y);
        e.z = __expf(p1.x); e.w = __expf(p1.y);
        prs[lv] = act ? (e.x + e.y) + (e.z + e.w) : 0.f;
        if (act && v < VN)
            *(float4*)(Erow + (size_t)v * VN + w4) = e;
    }
    #pragma unroll
    for (int lv = 0; lv < 16; lv++) {
        #pragma unroll
        for (int o = 16; o > 0; o >>= 1)
            prs[lv] += __shfl_xor_sync(0xffffffffu, prs[lv], o);
    }
    if (lam == 0) {
        #pragma unroll
        for (int lv = 0; lv < 16; lv++) red[wp * 16 + lv] = prs[lv];
    }
    __syncthreads();
    if (t < 32) {
        int h = t >> 4, lv = t & 15;
        float sum = red[(h * 4 + 0) * 16 + lv] + red[(h * 4 + 1) * 16 + lv]
                  + red[(h * 4 + 2) * 16 + lv] + red[(h * 4 + 3) * 16 + lv];
        int v = vbase + h * 16 + lv;
        if (v < VN) Ro[(size_t)s * VN + v] = sum;
    }
}

// Fused double diffusion: both GDEP steps, all 32 channels resident.
// grid (NSL, 2 sides), block 256, 2 CTAs/SM (smem 104000B).
// t<128 -> ch 0..15, t>=128 -> ch 16..31; within half u<100 owns w-quad 4u.
__global__ __launch_bounds__(256, 2) void kd(const float* __restrict__ E1,
                                             const float* __restrict__ Rr1,
                                             const float* __restrict__ E2,
                                             const float* __restrict__ Rr2,
                                             float* __restrict__ Ho1a,
                                             float* __restrict__ Ho1b,
                                             float* __restrict__ Ho2a,
                                             float* __restrict__ Ho2b) {
    extern __shared__ float smf[];
    float* rinv = smf;              // 400
    u64* hs2 = (u64*)(smf + VN);    // [32][400] pk2(H/R)
    int s = blockIdx.x, side = blockIdx.y, t = threadIdx.x;
    const float* Em = side ? E2 : E1;
    const float* Rm = side ? Rr2 : Rr1;
    float* Hoa = side ? Ho2a : Ho1a;
    float* Hob = side ? Ho2b : Ho1b;
    for (int i = t; i < VN; i += 256) rinv[i] = 1.0f / Rm[(size_t)s * VN + i];
    __syncthreads();
    const float* Xb = g_Xt + (size_t)s * SLC;
    for (int i = t; i < SLC; i += 256)
        hs2[i] = pk2(Xb[i] * rinv[i % VN]);
    __syncthreads();

    int half = t >> 7, u = t & 127;
    bool act = (u < 100);
    int w4 = act ? u * 4 : 0;
    int cbase = half * 16;
    const float* Eb = Em + (size_t)s * ESL;

    for (int step = 0; step < 2; step++) {
        u64 acc[16][2];
        #pragma unroll
        for (int c = 0; c < 16; c++) { acc[c][0] = 0; acc[c][1] = 0; }
        if (act) {
            ull2 c0 = *(const ull2*)(Eb + w4);
            ull2 c1 = *(const ull2*)(Eb + VN + w4);
            for (int v = 0; v < VN; v += 2) {
                int vn = (v + 2 < VN) ? v + 2 : 0;
                ull2 n0 = *(const ull2*)(Eb + (size_t)vn * VN + w4);
                ull2 n1 = *(const ull2*)(Eb + (size_t)(vn + 1) * VN + w4);
                #pragma unroll
                for (int c = 0; c < 16; c++) {
                    ull2 h = *(const ull2*)&hs2[(cbase + c) * VN + v];
                    fma2(acc[c][0], h.x, c0.x);
                    fma2(acc[c][1], h.x, c0.y);
                    fma2(acc[c][0], h.y, c1.x);
                    fma2(acc[c][1], h.y, c1.y);
                }
                c0 = n0; c1 = n1;
            }
        }
        __syncthreads();   // all reads of hs2 complete before repack
        if (act) {
            float* Ob = (step == 0 ? Hoa : Hob) + (size_t)s * SLC;
            float r0 = rinv[w4], r1_ = rinv[w4 + 1];
            float r2_ = rinv[w4 + 2], r3_ = rinv[w4 + 3];
            #pragma unroll
            for (int c = 0; c < 16; c++) {
                int ch = cbase + c;
                float4 xv = *(const float4*)(Xb + ch * VN + w4);
                float2 p0 = up2(acc[c][0]), p1 = up2(acc[c][1]);
                float4 r;
                r.x = 0.05f * xv.x + 0.95f * p0.x;
                r.y = 0.05f * xv.y + 0.95f * p0.y;
                r.z = 0.05f * xv.z + 0.95f * p1.x;
                r.w = 0.05f * xv.w + 0.95f * p1.y;
                *(float4*)(Ob + ch * VN + w4) = r;
                if (step == 0) {
                    hs2[ch * VN + w4 + 0] = pk2(r.x * r0);
                    hs2[ch * VN + w4 + 1] = pk2(r.y * r1_);
                    hs2[ch * VN + w4 + 2] = pk2(r.z * r2_);
                    hs2[ch * VN + w4 + 3] = pk2(r.w * r3_);
                }
            }
        }
        __syncthreads();   // repacked hs2 visible before step 2
    }
}

// out = b1+b2 + (Wm1x+Wm2x)Xt + Wm1a*H1a + Wm1b*H1b + Wm2a*H2a + Wm2b*H2b
__global__ __launch_bounds__(256) void k_mlp(const float* __restrict__ w1,
                                             const float* __restrict__ b1,
                                             const float* __restrict__ w2,
                                             const float* __restrict__ b2,
                                             float* __restrict__ out) {
    __shared__ float wxc[1024], wa1[2048], wa2[2048], bs[32];
    int s = blockIdx.x, t = threadIdx.x;
    int n = s / LL, l = s - n * LL;
    for (int i = t; i < 1024; i += 256) {
        int o = i >> 5, c = i & 31;
        wxc[i] = w1[o * 96 + c] + w2[o * 96 + c];
    }
    for (int i = t; i < 2048; i += 256) {
        int o = i >> 6, c = i & 63;
        wa1[i] = w1[o * 96 + 32 + c];
        wa2[i] = w2[o * 96 + 32 + c];
    }
    if (t < 32) bs[t] = b1[t] + b2[t];
    __syncthreads();
    size_t sb = (size_t)s * SLC;
    const float4* Xt4 = (const float4*)(g_Xt  + sb);
    const float4* A14 = (const float4*)(g_H1a + sb);
    const float4* B14 = (const float4*)(g_H1b + sb);
    const float4* A24 = (const float4*)(g_H2a + sb);
    const float4* B24 = (const float4*)(g_H2b + sb);
    for (int qd = t; qd < 3200; qd += 256) {
        int o = qd / 100, vq = qd - o * 100;
        float bz = bs[o];
        float4 a; a.x = bz; a.y = bz; a.z = bz; a.w = bz;
        #pragma unroll 8
        for (int c = 0; c < 32; c++) {
            int idx = c * 100 + vq;
            float4 xv = Xt4[idx];
            float w = wxc[o * 32 + c];
            a.x += w * xv.x; a.y += w * xv.y; a.z += w * xv.z; a.w += w * xv.w;
            float4 h1 = A14[idx];
            w = wa1[o * 64 + c];
            a.x += w * h1.x; a.y += w * h1.y; a.z += w * h1.z; a.w += w * h1.w;
            float4 h1b = B14[idx];
            w = wa1[o * 64 + 32 + c];
            a.x += w * h1b.x; a.y += w * h1b.y; a.z += w * h1b.z; a.w += w * h1b.w;
            float4 h2 = A24[idx];
            w = wa2[o * 64 + c];
            a.x += w * h2.x; a.y += w * h2.y; a.z += w * h2.z; a.w += w * h2.w;
            float4 h2b = B24[idx];
            w = wa2[o * 64 + 32 + c];
            a.x += w * h2b.x; a.y += w * h2b.y; a.z += w * h2b.z; a.w += w * h2b.w;
        }
        int v = vq * 4;
        size_t ob = ((size_t)(n * CH + o) * VN + v) * LL + l;
        out[ob]          = a.x;
        out[ob + LL]     = a.y;
        out[ob + 2 * LL] = a.z;
        out[ob + 3 * LL] = a.w;
    }
}

extern "C" void kernel_launch(void* const* d_in, const int* in_sizes, int n_in,
                              void* d_out, int out_size) {
    const float* x   = (const float*)d_in[0];
    const float* wl1 = (const float*)d_in[1];
    const float* bl1 = (const float*)d_in[2];
    const float* wl2 = (const float*)d_in[3];
    const float* bl2 = (const float*)d_in[4];
    const float* wm1 = (const float*)d_in[5];
    const float* bm1 = (const float*)d_in[6];
    const float* wm2 = (const float*)d_in[7];
    const float* bm2 = (const float*)d_in[8];
    float* out = (float*)d_out;

    const int dsm = VN * 4 + SLC * 8;   // 104000 B
    static bool attr_done = false;
    if (!attr_done) {
        cudaFuncSetAttribute(kd, cudaFuncAttributeMaxDynamicSharedMemorySize, dsm);
        attr_done = true;
    }

    float *E, *ET, *R1, *R2, *X1, *X2, *H1a, *H1b, *H2a, *H2b;
    cudaGetSymbolAddress((void**)&E,  g_E);
    cudaGetSymbolAddress((void**)&ET, g_ET);
    cudaGetSymbolAddress((void**)&R1, g_R1);
    cudaGetSymbolAddress((void**)&R2, g_R2);
    cudaGetSymbolAddress((void**)&X1, g_X1);
    cudaGetSymbolAddress((void**)&X2, g_X2);
    cudaGetSymbolAddress((void**)&H1a, g_H1a);
    cudaGetSymbolAddress((void**)&H1b, g_H1b);
    cudaGetSymbolAddress((void**)&H2a, g_H2a);
    cudaGetSymbolAddress((void**)&H2b, g_H2b);

    k_tr<<<1600, 256>>>(x);
    k_conv<<<NSL, 256>>>(wl1, bl1, wl2, bl2);
    k2<<<dim3(13, NSL, 2), 256>>>(X1, X2, E, R1, ET, R2);
    kd<<<dim3(NSL, 2), 256, dsm>>>(E, R1, ET, R2, H1a, H1b, H2a, H2b);
    k_mlp<<<NSL, 256>>>(wm1, bm1, wm2, bm2, out);
}